// round 3
// baseline (speedup 1.0000x reference)
#include <cuda_runtime.h>
#include <stdint.h>
#include <math.h>

#define NB 64
#define NC 512
#define HW 1024
#define NE 16
#define TABLE 65536   // 2048*32 per expert
#define POOL_BLOCKS 4096

// ---------------- scratch (allocation-free: __device__ globals) ----------------
__device__ float g_x[NB * NC];     // pooled activations
__device__ int   g_i0[NB];         // top-1 expert per batch
__device__ int   g_i1[NB];         // top-2 expert per batch
__device__ float g_p0[NB];         // top-1 prob
__device__ float g_p1[NB];         // top-2 prob
__device__ float g_z[NB];          // lse^2 per batch
__device__ int   g_ctr0 = 0;       // pool-done counter
__device__ int   g_ctr1 = 0;       // router-done counter
__device__ int   g_ctr2 = 0;       // combine-done counter (for reset)

// ---------------- threefry2x32 (JAX-compatible) ----------------
__device__ __forceinline__ uint32_t rotl32(uint32_t x, int d) {
    return (x << d) | (x >> (32 - d));
}

__device__ __forceinline__ void threefry2x32(uint32_t k0, uint32_t k1,
                                             uint32_t x0, uint32_t x1,
                                             uint32_t* o0, uint32_t* o1) {
    const uint32_t ks0 = k0, ks1 = k1, ks2 = k0 ^ k1 ^ 0x1BD11BDAu;
    uint32_t a = x0 + ks0, b = x1 + ks1;
    const int r0[4] = {13, 15, 26, 6};
    const int r1[4] = {17, 29, 16, 24};
#define TF_ROUND4(R) \
    { a += b; b = rotl32(b, (R)[0]); b ^= a; \
      a += b; b = rotl32(b, (R)[1]); b ^= a; \
      a += b; b = rotl32(b, (R)[2]); b ^= a; \
      a += b; b = rotl32(b, (R)[3]); b ^= a; }
    TF_ROUND4(r0); a += ks1; b += ks2 + 1u;
    TF_ROUND4(r1); a += ks2; b += ks0 + 2u;
    TF_ROUND4(r0); a += ks0; b += ks1 + 3u;
    TF_ROUND4(r1); a += ks1; b += ks2 + 4u;
    TF_ROUND4(r0); a += ks2; b += ks0 + 5u;
#undef TF_ROUND4
    *o0 = a; *o1 = b;
}

// eps[j] for flat j in [0, 1024): jax.random.normal(key(42), (64,16))
__device__ __forceinline__ float jax_normal_eps(int j) {
    uint32_t o0, o1, bits;
    if (j < 512) {
        threefry2x32(0u, 42u, (uint32_t)j, (uint32_t)(j + 512), &o0, &o1);
        bits = o0;
    } else {
        threefry2x32(0u, 42u, (uint32_t)(j - 512), (uint32_t)j, &o0, &o1);
        bits = o1;
    }
    float f = __uint_as_float((bits >> 9) | 0x3f800000u) - 1.0f;   // [0,1)
    const float lo = __uint_as_float(0xBF7FFFFFu);                 // nextafter(-1,0)
    float u = fmaxf(lo, f * 2.0f + lo);                            // hi-lo == 2.0f
    return 1.4142135623730951f * erfinvf(u);
}

__device__ __forceinline__ float softplus_f(float x) {
    return fmaxf(x, 0.0f) + log1pf(expf(-fabsf(x)));
}

// thread-0 spin on a global counter, then block-wide acquire
__device__ __forceinline__ void block_wait(int* ctr, int target) {
    if (threadIdx.x == 0) {
        while (atomicAdd(ctr, 0) < target) __nanosleep(128);
        __threadfence();
    }
    __syncthreads();
}

// ---------------- the single fused kernel ----------------
__global__ void __launch_bounds__(256) k_fused(
    const float* __restrict__ in,
    const float* __restrict__ Wr, const float* __restrict__ br,
    const float* __restrict__ Wn, const float* __restrict__ bn,
    const float* __restrict__ A, float* __restrict__ out)
{
    const int bid = blockIdx.x, tid = threadIdx.x;
    const int warp = tid >> 5, lane = tid & 31;

    // ===== Stage 1: mean pool (all 4096 blocks, warp per row, 8 rows/block) =====
    {
        int row = bid * 8 + warp;
        const float4* p = (const float4*)(in + (size_t)row * HW);
        float s = 0.0f;
#pragma unroll
        for (int i = 0; i < 8; i++) {
            float4 v = __ldcs(&p[lane + i * 32]);
            s += (v.x + v.y) + (v.z + v.w);
        }
#pragma unroll
        for (int o = 16; o > 0; o >>= 1) s += __shfl_down_sync(0xffffffffu, s, o);
        if (lane == 0) g_x[row] = s * (1.0f / 1024.0f);
    }
    __syncthreads();
    if (tid == 0) { __threadfence(); atomicAdd(&g_ctr0, 1); }

    if (bid >= 128) return;   // pure pool blocks

    if (bid < 64) {
        // ===== Stage 2: dual GEMV + router for batch b = bid (64 blocks) =====
        const int b = bid;
        __shared__ float xs[NC];
        __shared__ float sr_s[NE], sn_s[NE];

        block_wait(&g_ctr0, POOL_BLOCKS);

        for (int i = tid; i < NC; i += 256) xs[i] = g_x[b * NC + i];
        __syncthreads();
#pragma unroll
        for (int t = 0; t < 2; t++) {
            int e = warp * 2 + t;
            float sr = 0.0f, sn = 0.0f;
            for (int c = lane; c < NC; c += 32) {
                float xv = xs[c];
                sr = fmaf(xv, __ldg(&Wr[c * NE + e]), sr);
                sn = fmaf(xv, __ldg(&Wn[c * NE + e]), sn);
            }
#pragma unroll
            for (int o = 16; o > 0; o >>= 1) {
                sr += __shfl_down_sync(0xffffffffu, sr, o);
                sn += __shfl_down_sync(0xffffffffu, sn, o);
            }
            if (lane == 0) {
                sr_s[e] = sr + __ldg(&br[e]);
                sn_s[e] = sn + __ldg(&bn[e]);
            }
        }
        __syncthreads();

        if (warp == 0) {
            bool act = lane < NE;
            float lg = act ? sr_s[lane] : -INFINITY;
            float nz = act ? sn_s[lane] : 0.0f;

            // softmax(route logits)
            float m = lg;
#pragma unroll
            for (int o = 16; o > 0; o >>= 1) m = fmaxf(m, __shfl_xor_sync(0xffffffffu, m, o));
            float el = act ? expf(lg - m) : 0.0f;
            float s = el;
#pragma unroll
            for (int o = 16; o > 0; o >>= 1) s += __shfl_xor_sync(0xffffffffu, s, o);
            float soft = el / s;

            // noise = softmax(eps * softplus(noise_logits))
            float pre = -INFINITY;
            if (act) {
                float eps = jax_normal_eps(b * NE + lane);
                pre = eps * softplus_f(nz);
            }
            float m2 = pre;
#pragma unroll
            for (int o = 16; o > 0; o >>= 1) m2 = fmaxf(m2, __shfl_xor_sync(0xffffffffu, m2, o));
            float ep = act ? expf(pre - m2) : 0.0f;
            float s2 = ep;
#pragma unroll
            for (int o = 16; o > 0; o >>= 1) s2 += __shfl_xor_sync(0xffffffffu, s2, o);

            float ny = act ? (soft + ep / s2) : -INFINITY;

            // argmax #1 (ties -> lower index)
            float v0 = ny; int i0 = lane;
#pragma unroll
            for (int o = 16; o > 0; o >>= 1) {
                float vo = __shfl_xor_sync(0xffffffffu, v0, o);
                int io = __shfl_xor_sync(0xffffffffu, i0, o);
                if (vo > v0 || (vo == v0 && io < i0)) { v0 = vo; i0 = io; }
            }
            // argmax #2 (exclude i0)
            float v1 = (lane == i0) ? -INFINITY : ny; int i1 = lane;
#pragma unroll
            for (int o = 16; o > 0; o >>= 1) {
                float vo = __shfl_xor_sync(0xffffffffu, v1, o);
                int io = __shfl_xor_sync(0xffffffffu, i1, o);
                if (vo > v1 || (vo == v1 && io < i1)) { v1 = vo; i1 = io; }
            }

            // logsumexp over noisy logits (v0 is the max)
            float ee = act ? expf(ny - v0) : 0.0f;
            float ss = ee;
#pragma unroll
            for (int o = 16; o > 0; o >>= 1) ss += __shfl_xor_sync(0xffffffffu, ss, o);

            if (lane == 0) {
                float lse = v0 + logf(ss);
                float e1 = expf(v1 - v0);
                float p0 = 1.0f / (1.0f + e1);
                g_i0[b] = i0; g_i1[b] = i1;
                g_p0[b] = p0; g_p1[b] = e1 * p0;
                g_z[b]  = lse * lse;
                __threadfence();
                atomicAdd(&g_ctr1, 1);
            }
        }
        return;
    }

    // ===== Stage 3: combine (blocks 64..127, 64 blocks x 256 threads) =====
    {
        __shared__ int   si0[NB], si1[NB];
        __shared__ float sp0[NB], sp1[NB];
        __shared__ float ws[NE];

        block_wait(&g_ctr1, NB);

        if (tid < NB) {
            si0[tid] = g_i0[tid]; si1[tid] = g_i1[tid];
            sp0[tid] = g_p0[tid]; sp1[tid] = g_p1[tid];
        }
        __syncthreads();
        if (tid < NE) {
            float w = 0.0f;
#pragma unroll 8
            for (int b = 0; b < NB; b++) {
                if (si0[b] == tid) w += sp0[b];
                if (si1[b] == tid) w += sp1[b];
            }
            ws[tid] = w * (1.0f / (float)NB);
        }
        if (bid == 64 && tid == 64) {
            float z = 0.0f;
#pragma unroll
            for (int b = 0; b < NB; b++) z += g_z[b];
            out[TABLE] = z * (1.0f / (float)NB);
        }
        __syncthreads();

        int idx = (bid - 64) * 256 + tid;   // float4 index in [0, 16384)
        const float4* A4 = (const float4*)A;
        float4 acc = make_float4(0.f, 0.f, 0.f, 0.f);
#pragma unroll
        for (int e = 0; e < NE; e++) {
            float4 v = __ldg(&A4[(size_t)e * (TABLE / 4) + idx]);
            float w = ws[e];
            acc.x = fmaf(w, v.x, acc.x);
            acc.y = fmaf(w, v.y, acc.y);
            acc.z = fmaf(w, v.z, acc.z);
            acc.w = fmaf(w, v.w, acc.w);
        }
        ((float4*)out)[idx] = acc;

        // last combine block resets counters for the next graph replay
        __syncthreads();
        if (tid == 0) {
            __threadfence();
            int old = atomicAdd(&g_ctr2, 1);
            if (old == 63) {
                atomicExch(&g_ctr0, 0);
                atomicExch(&g_ctr1, 0);
                atomicExch(&g_ctr2, 0);
            }
        }
    }
}

// ---------------- launch ----------------
extern "C" void kernel_launch(void* const* d_in, const int* in_sizes, int n_in,
                              void* d_out, int out_size) {
    const float* inputs  = (const float*)d_in[0];  // [64,512,32,32]
    const float* W_route = (const float*)d_in[1];  // [512,16]
    const float* b_route = (const float*)d_in[2];  // [16]
    const float* W_noise = (const float*)d_in[3];  // [512,16]
    const float* b_noise = (const float*)d_in[4];  // [16]
    const float* A_logs  = (const float*)d_in[5];  // [16,2048,32]
    float* out = (float*)d_out;

    k_fused<<<POOL_BLOCKS, 256>>>(inputs, W_route, b_route, W_noise, b_noise,
                                  A_logs, out);
}